// round 1
// baseline (speedup 1.0000x reference)
#include <cuda_runtime.h>
#include <cstdint>
#include <cstddef>

#define NTOK   49
#define CDIM   128
#define HEADS  4
#define HD     32
#define XROW   132   // xs / O row stride (floats)
#define QROW   36    // q/k row stride
#define VROW   60    // vt row stride (per d)
#define PROW   60    // P row stride

// shared-memory layout (float offsets)
#define OFF_XS   0                                  // 64*132   = 8448  (x tile, later O tile)
#define OFF_Q    (OFF_XS + 64 * XROW)               // 4*64*36  = 9216
#define OFF_K    (OFF_Q + HEADS * 64 * QROW)        // 4*56*36  = 8064
#define OFF_VT   (OFF_K + HEADS * 56 * QROW)        // 4*32*60  = 7680
#define OFF_P    (OFF_VT + HEADS * HD * VROW)       // 4*64*60  = 15360 (also weight staging)
#define OFF_MASK (OFF_P + HEADS * 64 * PROW)        // 2401
#define OFF_BIAS (OFF_MASK + NTOK * NTOK)           // 676
#define OFF_RIDX (OFF_BIAS + 169 * HEADS)           // 2401 ints
#define SMEM_FLOATS (OFF_RIDX + NTOK * NTOK)        // 54246 floats
#define SMEM_BYTES  (SMEM_FLOATS * 4)               // 216984 bytes

__device__ __forceinline__ float tf32r(float x) {
    uint32_t u;
    asm("cvt.rna.tf32.f32 %0, %1;" : "=r"(u) : "f"(x));
    return __uint_as_float(u);
}

__device__ __forceinline__ void mma8(float* d, const uint32_t* a, const uint32_t* b) {
    asm volatile(
        "mma.sync.aligned.m16n8k8.row.col.f32.tf32.tf32.f32 "
        "{%0,%1,%2,%3}, {%4,%5,%6,%7}, {%8,%9}, {%0,%1,%2,%3};\n"
        : "+f"(d[0]), "+f"(d[1]), "+f"(d[2]), "+f"(d[3])
        : "r"(a[0]), "r"(a[1]), "r"(a[2]), "r"(a[3]), "r"(b[0]), "r"(b[1]));
}

__global__ __launch_bounds__(256, 1)
void lpwin_kernel(const float* __restrict__ x,
                  const float* __restrict__ mask,
                  const float* __restrict__ qkv_w,
                  const float* __restrict__ proj_w,
                  const float* __restrict__ proj_b,
                  const float* __restrict__ bias_table,
                  const float* __restrict__ alpha,
                  const int*   __restrict__ rel_idx,
                  float* __restrict__ out,
                  int nwin)
{
    extern __shared__ float sm[];
    const int b    = blockIdx.x;
    const int tid  = threadIdx.x;
    const int wid  = tid >> 5;
    const int lane = tid & 31;
    const int g    = lane >> 2;   // mma groupID
    const int t    = lane & 3;    // mma threadID-in-group

    float* xs = sm + OFF_XS;
    float* Qs = sm + OFF_Q;
    float* Ks = sm + OFF_K;
    float* Vs = sm + OFF_VT;
    float* Ps = sm + OFF_P;
    float* Ws = sm + OFF_P;       // weight staging aliases P (live ranges disjoint)
    float* Ms = sm + OFF_MASK;
    float* Bt = sm + OFF_BIAS;
    int*   Ri = (int*)(sm + OFF_RIDX);

    // ---------------- Phase 1: stage inputs ----------------
    const float* xb = x + (size_t)b * (NTOK * CDIM);
    for (int i = tid; i < NTOK * 32; i += 256) {
        int r = i >> 5, c4 = (i & 31) << 2;
        float4 v = *(const float4*)(xb + r * CDIM + c4);
        v.x = tf32r(v.x); v.y = tf32r(v.y); v.z = tf32r(v.z); v.w = tf32r(v.w);
        *(float4*)(xs + r * XROW + c4) = v;
    }
    for (int i = tid; i < HEADS * HD * VROW; i += 256) Vs[i] = 0.f;  // zero incl. k-pad cols
    {
        const int widx = b % nwin;
        const float* mb = mask + (size_t)widx * (NTOK * NTOK);
        for (int i = tid; i < NTOK * NTOK; i += 256) Ms[i] = mb[i];
    }
    for (int i = tid; i < NTOK * NTOK; i += 256) Ri[i] = rel_idx[i];
    for (int i = tid; i < 169 * HEADS; i += 256) Bt[i] = bias_table[i];
    __syncthreads();

    // ---------------- Phase 2: QKV GEMM (tf32 mma), W streamed via smem ----------------
    {
        float acc[4][6][4];
        #pragma unroll
        for (int mt = 0; mt < 4; ++mt)
            #pragma unroll
            for (int nt = 0; nt < 6; ++nt)
                #pragma unroll
                for (int e = 0; e < 4; ++e) acc[mt][nt][e] = 0.f;

        const int n0 = wid * 48;      // each warp owns 48 output columns of 384
        for (int kc = 0; kc < 4; ++kc) {          // k-chunks of 32
            for (int i = tid; i < 384 * 8; i += 256) {
                int n = i >> 3, q4 = (i & 7) << 2;
                float4 v = *(const float4*)(qkv_w + n * CDIM + kc * 32 + q4);
                v.x = tf32r(v.x); v.y = tf32r(v.y); v.z = tf32r(v.z); v.w = tf32r(v.w);
                *(float4*)(Ws + n * QROW + q4) = v;
            }
            __syncthreads();
            #pragma unroll
            for (int k8 = 0; k8 < 4; ++k8) {
                const int kk = k8 * 8;
                uint32_t bf[6][2];
                #pragma unroll
                for (int nt = 0; nt < 6; ++nt) {
                    const float* bp = Ws + (n0 + nt * 8 + g) * QROW + kk + t;
                    bf[nt][0] = __float_as_uint(bp[0]);
                    bf[nt][1] = __float_as_uint(bp[4]);
                }
                #pragma unroll
                for (int mt = 0; mt < 4; ++mt) {
                    const float* ap = xs + (mt * 16 + g) * XROW + kc * 32 + kk + t;
                    uint32_t af[4];
                    af[0] = __float_as_uint(ap[0]);
                    af[1] = __float_as_uint(ap[8 * XROW]);
                    af[2] = __float_as_uint(ap[4]);
                    af[3] = __float_as_uint(ap[8 * XROW + 4]);
                    #pragma unroll
                    for (int nt = 0; nt < 6; ++nt) mma8(acc[mt][nt], af, bf[nt]);
                }
            }
            __syncthreads();
        }
        // scatter C fragments to Q / K / V^T
        #pragma unroll
        for (int mt = 0; mt < 4; ++mt)
            #pragma unroll
            for (int nt = 0; nt < 6; ++nt)
                #pragma unroll
                for (int e = 0; e < 4; ++e) {
                    int row = mt * 16 + g + (e >> 1) * 8;
                    if (row >= NTOK) continue;
                    int n = n0 + nt * 8 + 2 * t + (e & 1);
                    float v = acc[mt][nt][e];
                    if (n < 128) {
                        Qs[(n >> 5) * 64 * QROW + row * QROW + (n & 31)] = v;
                    } else if (n < 256) {
                        int m = n - 128;
                        Ks[(m >> 5) * 56 * QROW + row * QROW + (m & 31)] = v;
                    } else {
                        int m = n - 256;
                        Vs[(m >> 5) * HD * VROW + (m & 31) * VROW + row] = tf32r(v);
                    }
                }
    }
    __syncthreads();

    // ---------------- Phase 3: per-head attention (2 warps / head) ----------------
    const int h   = wid >> 1;
    const int sub = wid & 1;
    float* Qh = Qs + h * 64 * QROW;
    float* Kh = Ks + h * 56 * QROW;
    float* Vh = Vs + h * HD * VROW;
    float* Ph = Ps + h * 64 * PROW;

    // 3a: L2 normalize (p=2); fold per-head alpha into q_hat
    {
        float  sc = sub ? 1.f : alpha[h];
        float* T  = sub ? Kh : Qh;
        for (int r = 0; r < NTOK; ++r) {
            float v  = T[r * QROW + lane];
            float ss = v * v;
            #pragma unroll
            for (int o = 16; o > 0; o >>= 1) ss += __shfl_xor_sync(0xffffffffu, ss, o);
            float inv = sc / (sqrtf(ss) + 1e-6f);
            T[r * QROW + lane] = tf32r(v * inv);
        }
    }
    __syncthreads();

    // 3b: S = alpha * q_hat k_hat^T + rpb + mask
    {
        const int ntBeg = sub ? 4 : 0;
        const int ntEnd = sub ? 7 : 4;
        for (int nt = ntBeg; nt < ntEnd; ++nt) {
            uint32_t bfv[4][2];
            #pragma unroll
            for (int k8 = 0; k8 < 4; ++k8) {
                const float* bp = Kh + (nt * 8 + g) * QROW + k8 * 8 + t;
                bfv[k8][0] = __float_as_uint(bp[0]);
                bfv[k8][1] = __float_as_uint(bp[4]);
            }
            #pragma unroll
            for (int mt = 0; mt < 4; ++mt) {
                float c[4] = {0.f, 0.f, 0.f, 0.f};
                #pragma unroll
                for (int k8 = 0; k8 < 4; ++k8) {
                    const float* ap = Qh + (mt * 16 + g) * QROW + k8 * 8 + t;
                    uint32_t af[4];
                    af[0] = __float_as_uint(ap[0]);
                    af[1] = __float_as_uint(ap[8 * QROW]);
                    af[2] = __float_as_uint(ap[4]);
                    af[3] = __float_as_uint(ap[8 * QROW + 4]);
                    mma8(c, af, bfv[k8]);
                }
                #pragma unroll
                for (int e = 0; e < 4; ++e) {
                    int i = mt * 16 + g + (e >> 1) * 8;
                    int j = nt * 8 + 2 * t + (e & 1);
                    float v = c[e];
                    if (i < NTOK && j < NTOK)
                        v += Bt[Ri[i * NTOK + j] * HEADS + h] + Ms[i * NTOK + j];
                    Ph[i * PROW + j] = v;
                }
            }
        }
    }
    __syncthreads();

    // 3c: row softmax over 49 valid cols; zero pad cols 49..55 (k-pad for PV mma)
    {
        const int r0 = sub ? 25 : 0;
        const int r1 = sub ? NTOK : 25;
        for (int i = r0; i < r1; ++i) {
            float s1 = Ph[i * PROW + lane];
            float s2 = (lane < 17) ? Ph[i * PROW + 32 + lane] : -1e30f;
            float m = fmaxf(s1, s2);
            #pragma unroll
            for (int o = 16; o > 0; o >>= 1) m = fmaxf(m, __shfl_xor_sync(0xffffffffu, m, o));
            float e1 = __expf(s1 - m);
            float e2 = (lane < 17) ? __expf(s2 - m) : 0.f;
            float s = e1 + e2;
            #pragma unroll
            for (int o = 16; o > 0; o >>= 1) s += __shfl_xor_sync(0xffffffffu, s, o);
            float inv = 1.f / s;
            Ph[i * PROW + lane] = tf32r(e1 * inv);
            if (lane < 24) Ph[i * PROW + 32 + lane] = (lane < 17) ? tf32r(e2 * inv) : 0.f;
        }
    }
    __syncthreads();

    // 3d: O = P V  (V^T layout), O written into xs region (tf32)
    {
        #pragma unroll
        for (int nn = 0; nn < 2; ++nn) {
            const int nt = sub * 2 + nn;
            uint32_t bfv[7][2];
            #pragma unroll
            for (int k8 = 0; k8 < 7; ++k8) {
                const float* bp = Vh + (nt * 8 + g) * VROW + k8 * 8 + t;
                bfv[k8][0] = __float_as_uint(bp[0]);
                bfv[k8][1] = __float_as_uint(bp[4]);
            }
            #pragma unroll
            for (int mt = 0; mt < 4; ++mt) {
                float c[4] = {0.f, 0.f, 0.f, 0.f};
                #pragma unroll
                for (int k8 = 0; k8 < 7; ++k8) {
                    const float* ap = Ph + (mt * 16 + g) * PROW + k8 * 8 + t;
                    uint32_t af[4];
                    af[0] = __float_as_uint(ap[0]);
                    af[1] = __float_as_uint(ap[8 * PROW]);
                    af[2] = __float_as_uint(ap[4]);
                    af[3] = __float_as_uint(ap[8 * PROW + 4]);
                    mma8(c, af, bfv[k8]);
                }
                #pragma unroll
                for (int e = 0; e < 4; ++e) {
                    int i = mt * 16 + g + (e >> 1) * 8;
                    if (i >= NTOK) continue;
                    int d = nt * 8 + 2 * t + (e & 1);
                    xs[i * XROW + h * HD + d] = tf32r(c[e]);
                }
            }
        }
    }
    __syncthreads();

    // ---------------- Phase 4: output projection + bias ----------------
    {
        float acc[4][2][4];
        #pragma unroll
        for (int mt = 0; mt < 4; ++mt)
            #pragma unroll
            for (int nt = 0; nt < 2; ++nt)
                #pragma unroll
                for (int e = 0; e < 4; ++e) acc[mt][nt][e] = 0.f;

        const int n0 = wid * 16;      // each warp owns 16 of 128 output cols
        for (int kc = 0; kc < 2; ++kc) {          // k-chunks of 64
            for (int i = tid; i < 128 * 16; i += 256) {
                int n = i >> 4, q4 = (i & 15) << 2;
                float4 v = *(const float4*)(proj_w + n * CDIM + kc * 64 + q4);
                v.x = tf32r(v.x); v.y = tf32r(v.y); v.z = tf32r(v.z); v.w = tf32r(v.w);
                *(float4*)(Ws + n * 68 + q4) = v;
            }
            __syncthreads();
            #pragma unroll
            for (int k8 = 0; k8 < 8; ++k8) {
                uint32_t bfv[2][2];
                #pragma unroll
                for (int nt = 0; nt < 2; ++nt) {
                    const float* bp = Ws + (n0 + nt * 8 + g) * 68 + k8 * 8 + t;
                    bfv[nt][0] = __float_as_uint(bp[0]);
                    bfv[nt][1] = __float_as_uint(bp[4]);
                }
                #pragma unroll
                for (int mt = 0; mt < 4; ++mt) {
                    const float* ap = xs + (mt * 16 + g) * XROW + kc * 64 + k8 * 8 + t;
                    uint32_t af[4];
                    af[0] = __float_as_uint(ap[0]);
                    af[1] = __float_as_uint(ap[8 * XROW]);
                    af[2] = __float_as_uint(ap[4]);
                    af[3] = __float_as_uint(ap[8 * XROW + 4]);
                    #pragma unroll
                    for (int nt = 0; nt < 2; ++nt) mma8(acc[mt][nt], af, bfv[nt]);
                }
            }
            __syncthreads();
        }
        // stash into xs, then coalesced float4 store with bias
        #pragma unroll
        for (int mt = 0; mt < 4; ++mt)
            #pragma unroll
            for (int nt = 0; nt < 2; ++nt)
                #pragma unroll
                for (int e = 0; e < 4; ++e) {
                    int row = mt * 16 + g + (e >> 1) * 8;
                    if (row >= NTOK) continue;
                    int col = n0 + nt * 8 + 2 * t + (e & 1);
                    xs[row * XROW + col] = acc[mt][nt][e];
                }
        __syncthreads();
        float* ob = out + (size_t)b * (NTOK * CDIM);
        for (int i = tid; i < NTOK * 32; i += 256) {
            int r = i >> 5, c4 = (i & 31) << 2;
            float4 v  = *(const float4*)(xs + r * XROW + c4);
            float4 pb = *(const float4*)(proj_b + c4);
            v.x += pb.x; v.y += pb.y; v.z += pb.z; v.w += pb.w;
            *(float4*)(ob + r * CDIM + c4) = v;
        }
    }
}

extern "C" void kernel_launch(void* const* d_in, const int* in_sizes, int n_in,
                              void* d_out, int out_size) {
    const float* x    = (const float*)d_in[0];
    const float* mask = (const float*)d_in[1];
    const float* qkvw = (const float*)d_in[2];
    const float* pw   = (const float*)d_in[3];
    const float* pb   = (const float*)d_in[4];
    const float* bt   = (const float*)d_in[5];
    const float* al   = (const float*)d_in[6];
    const int*   ri   = (const int*)d_in[7];
    float* out = (float*)d_out;

    int B  = in_sizes[0] / (NTOK * CDIM);
    int NW = in_sizes[1] / (NTOK * NTOK);

    cudaFuncSetAttribute(lpwin_kernel, cudaFuncAttributeMaxDynamicSharedMemorySize, SMEM_BYTES);
    lpwin_kernel<<<B, 256, SMEM_BYTES>>>(x, mask, qkvw, pw, pb, bt, al, ri, out, NW);
}

// round 2
// speedup vs baseline: 1.3538x; 1.3538x over previous
#include <cuda_runtime.h>
#include <cstdint>
#include <cstddef>

#define NTOK   49
#define CDIM   128
#define HEADS  4
#define HD     32
#define XROW   132   // xs / O row stride (floats)
#define QROW   36    // q/k row stride
#define VROW   60    // vt row stride (per d)
#define PROW   60    // P row stride
#define NTHR   512

// shared-memory layout (float offsets)
#define OFF_XS   0                                  // 64*132   = 8448  (x tile, later O tile)
#define OFF_Q    (OFF_XS + 64 * XROW)               // 4*64*36  = 9216
#define OFF_K    (OFF_Q + HEADS * 64 * QROW)        // 4*56*36  = 8064
#define OFF_VT   (OFF_K + HEADS * 56 * QROW)        // 4*32*60  = 7680
#define OFF_P    (OFF_VT + HEADS * HD * VROW)       // 4*64*60  = 15360 (also weight staging)
#define OFF_MASK (OFF_P + HEADS * 64 * PROW)        // 2401
#define OFF_BIAS (OFF_MASK + NTOK * NTOK)           // 676
#define OFF_RIDX (OFF_BIAS + 169 * HEADS)           // 2401 ints
#define SMEM_FLOATS (OFF_RIDX + NTOK * NTOK)        // 54246 floats
#define SMEM_BYTES  (SMEM_FLOATS * 4)               // 216984 bytes

__device__ __forceinline__ float tf32r(float x) {
    uint32_t u;
    asm("cvt.rna.tf32.f32 %0, %1;" : "=r"(u) : "f"(x));
    return __uint_as_float(u);
}

__device__ __forceinline__ void mma8(float* d, const uint32_t* a, const uint32_t* b) {
    asm volatile(
        "mma.sync.aligned.m16n8k8.row.col.f32.tf32.tf32.f32 "
        "{%0,%1,%2,%3}, {%4,%5,%6,%7}, {%8,%9}, {%0,%1,%2,%3};\n"
        : "+f"(d[0]), "+f"(d[1]), "+f"(d[2]), "+f"(d[3])
        : "r"(a[0]), "r"(a[1]), "r"(a[2]), "r"(a[3]), "r"(b[0]), "r"(b[1]));
}

__global__ __launch_bounds__(NTHR, 1)
void lpwin_kernel(const float* __restrict__ x,
                  const float* __restrict__ mask,
                  const float* __restrict__ qkv_w,
                  const float* __restrict__ proj_w,
                  const float* __restrict__ proj_b,
                  const float* __restrict__ bias_table,
                  const float* __restrict__ alpha,
                  const int*   __restrict__ rel_idx,
                  float* __restrict__ out,
                  int nwin)
{
    extern __shared__ float sm[];
    const int b    = blockIdx.x;
    const int tid  = threadIdx.x;
    const int wid  = tid >> 5;    // 0..15
    const int lane = tid & 31;
    const int g    = lane >> 2;   // mma groupID
    const int t    = lane & 3;    // mma threadID-in-group

    float* xs = sm + OFF_XS;
    float* Qs = sm + OFF_Q;
    float* Ks = sm + OFF_K;
    float* Vs = sm + OFF_VT;
    float* Ps = sm + OFF_P;
    float* Ws = sm + OFF_P;       // weight staging aliases P (live ranges disjoint)
    float* Ms = sm + OFF_MASK;
    float* Bt = sm + OFF_BIAS;
    int*   Ri = (int*)(sm + OFF_RIDX);

    // ---------------- Phase 1: stage inputs ----------------
    const float* xb = x + (size_t)b * (NTOK * CDIM);
    for (int i = tid; i < NTOK * 32; i += NTHR) {
        int r = i >> 5, c4 = (i & 31) << 2;
        float4 v = *(const float4*)(xb + r * CDIM + c4);
        v.x = tf32r(v.x); v.y = tf32r(v.y); v.z = tf32r(v.z); v.w = tf32r(v.w);
        *(float4*)(xs + r * XROW + c4) = v;
    }
    for (int i = tid; i < HEADS * HD * VROW; i += NTHR) Vs[i] = 0.f;  // zero incl. k-pad cols
    {
        const int widx = b % nwin;
        const float* mb = mask + (size_t)widx * (NTOK * NTOK);
        for (int i = tid; i < NTOK * NTOK; i += NTHR) Ms[i] = mb[i];
    }
    for (int i = tid; i < NTOK * NTOK; i += NTHR) Ri[i] = rel_idx[i];
    for (int i = tid; i < 169 * HEADS; i += NTHR) Bt[i] = bias_table[i];
    __syncthreads();

    // ---------------- Phase 2: QKV GEMM (tf32 mma), W streamed via smem ----------------
    {
        float acc[4][3][4];
        #pragma unroll
        for (int mt = 0; mt < 4; ++mt)
            #pragma unroll
            for (int nt = 0; nt < 3; ++nt)
                #pragma unroll
                for (int e = 0; e < 4; ++e) acc[mt][nt][e] = 0.f;

        const int n0 = wid * 24;      // each warp owns 24 output columns of 384
        for (int kc = 0; kc < 4; ++kc) {          // k-chunks of 32
            for (int i = tid; i < 384 * 8; i += NTHR) {
                int n = i >> 3, q4 = (i & 7) << 2;
                float4 v = *(const float4*)(qkv_w + n * CDIM + kc * 32 + q4);
                v.x = tf32r(v.x); v.y = tf32r(v.y); v.z = tf32r(v.z); v.w = tf32r(v.w);
                *(float4*)(Ws + n * QROW + q4) = v;
            }
            __syncthreads();
            #pragma unroll
            for (int k8 = 0; k8 < 4; ++k8) {
                const int kk = k8 * 8;
                uint32_t bf[3][2];
                #pragma unroll
                for (int nt = 0; nt < 3; ++nt) {
                    const float* bp = Ws + (n0 + nt * 8 + g) * QROW + kk + t;
                    bf[nt][0] = __float_as_uint(bp[0]);
                    bf[nt][1] = __float_as_uint(bp[4]);
                }
                #pragma unroll
                for (int mt = 0; mt < 4; ++mt) {
                    const float* ap = xs + (mt * 16 + g) * XROW + kc * 32 + kk + t;
                    uint32_t af[4];
                    af[0] = __float_as_uint(ap[0]);
                    af[1] = __float_as_uint(ap[8 * XROW]);
                    af[2] = __float_as_uint(ap[4]);
                    af[3] = __float_as_uint(ap[8 * XROW + 4]);
                    #pragma unroll
                    for (int nt = 0; nt < 3; ++nt) mma8(acc[mt][nt], af, bf[nt]);
                }
            }
            __syncthreads();
        }
        // scatter C fragments to Q / K / V^T
        #pragma unroll
        for (int mt = 0; mt < 4; ++mt)
            #pragma unroll
            for (int nt = 0; nt < 3; ++nt)
                #pragma unroll
                for (int e = 0; e < 4; ++e) {
                    int row = mt * 16 + g + (e >> 1) * 8;
                    if (row >= NTOK) continue;
                    int n = n0 + nt * 8 + 2 * t + (e & 1);
                    float v = acc[mt][nt][e];
                    if (n < 128) {
                        Qs[(n >> 5) * 64 * QROW + row * QROW + (n & 31)] = v;
                    } else if (n < 256) {
                        int m = n - 128;
                        Ks[(m >> 5) * 56 * QROW + row * QROW + (m & 31)] = v;
                    } else {
                        int m = n - 256;
                        Vs[(m >> 5) * HD * VROW + (m & 31) * VROW + row] = tf32r(v);
                    }
                }
    }
    __syncthreads();

    // ---------------- Phase 3: per-head attention (4 warps / head) ----------------
    const int h   = wid >> 2;
    const int sub = wid & 3;
    float* Qh = Qs + h * 64 * QROW;
    float* Kh = Ks + h * 56 * QROW;
    float* Vh = Vs + h * HD * VROW;
    float* Ph = Ps + h * 64 * PROW;

    // 3a: L2 normalize (p=2); alpha folded into q_hat. 4-row ILP to hide SHFL latency.
    {
        const bool isQ = (sub < 2);
        const float sc = isQ ? alpha[h] : 1.f;
        float* T = isQ ? Qh : Kh;
        const int rs = (sub & 1) ? 25 : 0;
        const int re = (sub & 1) ? NTOK : 25;
        for (int r = rs; r < re; r += 4) {
            float v[4], ss[4]; int rr[4];
            #pragma unroll
            for (int j = 0; j < 4; ++j) {
                rr[j] = min(r + j, re - 1);
                v[j]  = T[rr[j] * QROW + lane];
                ss[j] = v[j] * v[j];
            }
            #pragma unroll
            for (int o = 16; o > 0; o >>= 1) {
                #pragma unroll
                for (int j = 0; j < 4; ++j) ss[j] += __shfl_xor_sync(0xffffffffu, ss[j], o);
            }
            #pragma unroll
            for (int j = 0; j < 4; ++j) {
                if (r + j < re) {
                    float inv = sc / (sqrtf(ss[j]) + 1e-6f);
                    T[rr[j] * QROW + lane] = tf32r(v[j] * inv);
                }
            }
        }
    }
    __syncthreads();

    // 3b: S = alpha * q_hat k_hat^T + rpb + mask   (7 n-tiles split 2/2/2/1 over 4 warps)
    {
        const int ntBeg = sub * 2;
        const int ntEnd = min(ntBeg + 2, 7);
        for (int nt = ntBeg; nt < ntEnd; ++nt) {
            uint32_t bfv[4][2];
            #pragma unroll
            for (int k8 = 0; k8 < 4; ++k8) {
                const float* bp = Kh + (nt * 8 + g) * QROW + k8 * 8 + t;
                bfv[k8][0] = __float_as_uint(bp[0]);
                bfv[k8][1] = __float_as_uint(bp[4]);
            }
            #pragma unroll
            for (int mt = 0; mt < 4; ++mt) {
                float c[4] = {0.f, 0.f, 0.f, 0.f};
                #pragma unroll
                for (int k8 = 0; k8 < 4; ++k8) {
                    const float* ap = Qh + (mt * 16 + g) * QROW + k8 * 8 + t;
                    uint32_t af[4];
                    af[0] = __float_as_uint(ap[0]);
                    af[1] = __float_as_uint(ap[8 * QROW]);
                    af[2] = __float_as_uint(ap[4]);
                    af[3] = __float_as_uint(ap[8 * QROW + 4]);
                    mma8(c, af, bfv[k8]);
                }
                #pragma unroll
                for (int e = 0; e < 4; ++e) {
                    int i = mt * 16 + g + (e >> 1) * 8;
                    int j = nt * 8 + 2 * t + (e & 1);
                    float v = c[e];
                    if (i < NTOK && j < NTOK)
                        v += Bt[Ri[i * NTOK + j] * HEADS + h] + Ms[i * NTOK + j];
                    Ph[i * PROW + j] = v;
                }
            }
        }
    }
    __syncthreads();

    // 3c: row softmax (no max-subtract: logits bounded by |alpha| + bias + mask),
    //     2-row ILP; zero pad cols 49..55 (k-pad for PV mma)
    {
        const int r0 = sub * 13;
        const int r1 = min(r0 + 13, NTOK);
        for (int i = r0; i < r1; i += 2) {
            const int ia = i;
            const int ib = min(i + 1, r1 - 1);
            const bool hasb = (i + 1 < r1);
            float e1a = __expf(Ph[ia * PROW + lane]);
            float e2a = (lane < 17) ? __expf(Ph[ia * PROW + 32 + lane]) : 0.f;
            float e1b = __expf(Ph[ib * PROW + lane]);
            float e2b = (lane < 17) ? __expf(Ph[ib * PROW + 32 + lane]) : 0.f;
            float sa = e1a + e2a;
            float sb = e1b + e2b;
            #pragma unroll
            for (int o = 16; o > 0; o >>= 1) {
                sa += __shfl_xor_sync(0xffffffffu, sa, o);
                sb += __shfl_xor_sync(0xffffffffu, sb, o);
            }
            float inva = 1.f / sa;
            Ph[ia * PROW + lane] = tf32r(e1a * inva);
            if (lane < 24) Ph[ia * PROW + 32 + lane] = (lane < 17) ? tf32r(e2a * inva) : 0.f;
            if (hasb) {
                float invb = 1.f / sb;
                Ph[ib * PROW + lane] = tf32r(e1b * invb);
                if (lane < 24) Ph[ib * PROW + 32 + lane] = (lane < 17) ? tf32r(e2b * invb) : 0.f;
            }
        }
    }
    __syncthreads();

    // 3d: O = P V  (V^T layout), one 8-col n-tile per warp, O written into xs (tf32)
    {
        const int nt = sub;
        uint32_t bfv[7][2];
        #pragma unroll
        for (int k8 = 0; k8 < 7; ++k8) {
            const float* bp = Vh + (nt * 8 + g) * VROW + k8 * 8 + t;
            bfv[k8][0] = __float_as_uint(bp[0]);
            bfv[k8][1] = __float_as_uint(bp[4]);
        }
        #pragma unroll
        for (int mt = 0; mt < 4; ++mt) {
            float c[4] = {0.f, 0.f, 0.f, 0.f};
            #pragma unroll
            for (int k8 = 0; k8 < 7; ++k8) {
                const float* ap = Ph + (mt * 16 + g) * PROW + k8 * 8 + t;
                uint32_t af[4];
                af[0] = __float_as_uint(ap[0]);
                af[1] = __float_as_uint(ap[8 * PROW]);
                af[2] = __float_as_uint(ap[4]);
                af[3] = __float_as_uint(ap[8 * PROW + 4]);
                mma8(c, af, bfv[k8]);
            }
            #pragma unroll
            for (int e = 0; e < 4; ++e) {
                int i = mt * 16 + g + (e >> 1) * 8;
                if (i >= NTOK) continue;
                int d = nt * 8 + 2 * t + (e & 1);
                xs[i * XROW + h * HD + d] = tf32r(c[e]);
            }
        }
    }
    __syncthreads();

    // ---------------- Phase 4: output projection + bias ----------------
    {
        float acc[4][4];
        #pragma unroll
        for (int mt = 0; mt < 4; ++mt)
            #pragma unroll
            for (int e = 0; e < 4; ++e) acc[mt][e] = 0.f;

        const int n0 = wid * 8;       // each warp owns 8 of 128 output cols
        for (int kc = 0; kc < 2; ++kc) {          // k-chunks of 64
            for (int i = tid; i < 128 * 16; i += NTHR) {
                int n = i >> 4, q4 = (i & 15) << 2;
                float4 v = *(const float4*)(proj_w + n * CDIM + kc * 64 + q4);
                v.x = tf32r(v.x); v.y = tf32r(v.y); v.z = tf32r(v.z); v.w = tf32r(v.w);
                *(float4*)(Ws + n * 68 + q4) = v;
            }
            __syncthreads();
            #pragma unroll
            for (int k8 = 0; k8 < 8; ++k8) {
                uint32_t bfv[2];
                const float* bp = Ws + (n0 + g) * 68 + k8 * 8 + t;
                bfv[0] = __float_as_uint(bp[0]);
                bfv[1] = __float_as_uint(bp[4]);
                #pragma unroll
                for (int mt = 0; mt < 4; ++mt) {
                    const float* ap = xs + (mt * 16 + g) * XROW + kc * 64 + k8 * 8 + t;
                    uint32_t af[4];
                    af[0] = __float_as_uint(ap[0]);
                    af[1] = __float_as_uint(ap[8 * XROW]);
                    af[2] = __float_as_uint(ap[4]);
                    af[3] = __float_as_uint(ap[8 * XROW + 4]);
                    mma8(acc[mt], af, bfv);
                }
            }
            __syncthreads();
        }
        // stash into xs, then coalesced float4 store with bias
        #pragma unroll
        for (int mt = 0; mt < 4; ++mt)
            #pragma unroll
            for (int e = 0; e < 4; ++e) {
                int row = mt * 16 + g + (e >> 1) * 8;
                if (row >= NTOK) continue;
                int col = n0 + 2 * t + (e & 1);
                xs[row * XROW + col] = acc[mt][e];
            }
        __syncthreads();
        float* ob = out + (size_t)b * (NTOK * CDIM);
        for (int i = tid; i < NTOK * 32; i += NTHR) {
            int r = i >> 5, c4 = (i & 31) << 2;
            float4 v  = *(const float4*)(xs + r * XROW + c4);
            float4 pb = *(const float4*)(proj_b + c4);
            v.x += pb.x; v.y += pb.y; v.z += pb.z; v.w += pb.w;
            *(float4*)(ob + r * CDIM + c4) = v;
        }
    }
}

extern "C" void kernel_launch(void* const* d_in, const int* in_sizes, int n_in,
                              void* d_out, int out_size) {
    const float* x    = (const float*)d_in[0];
    const float* mask = (const float*)d_in[1];
    const float* qkvw = (const float*)d_in[2];
    const float* pw   = (const float*)d_in[3];
    const float* pb   = (const float*)d_in[4];
    const float* bt   = (const float*)d_in[5];
    const float* al   = (const float*)d_in[6];
    const int*   ri   = (const int*)d_in[7];
    float* out = (float*)d_out;

    int B  = in_sizes[0] / (NTOK * CDIM);
    int NW = in_sizes[1] / (NTOK * NTOK);

    cudaFuncSetAttribute(lpwin_kernel, cudaFuncAttributeMaxDynamicSharedMemorySize, SMEM_BYTES);
    lpwin_kernel<<<B, NTHR, SMEM_BYTES>>>(x, mask, qkvw, pw, pb, bt, al, ri, out, NW);
}

// round 4
// speedup vs baseline: 1.5539x; 1.1478x over previous
#include <cuda_runtime.h>
#include <cstdint>
#include <cstddef>

#define NTOK   49
#define CDIM   128
#define HEADS  4
#define HD     32
#define XROW   132   // xs / O row stride (floats)
#define QROW   36    // q/k row stride
#define VROW   60    // vt row stride (per d)
#define PROW   60    // P row stride
#define NTHR   1024

// shared-memory layout (float offsets)
#define OFF_XS   0                                  // 64*132   = 8448  (x tile, later O tile)
#define OFF_Q    (OFF_XS + 64 * XROW)               // 4*64*36  = 9216
#define OFF_K    (OFF_Q + HEADS * 64 * QROW)        // 4*56*36  = 8064
#define OFF_VT   (OFF_K + HEADS * 56 * QROW)        // 4*32*60  = 7680
#define OFF_P    (OFF_VT + HEADS * HD * VROW)       // 4*64*60  = 15360 (also weight staging)
#define OFF_MASK (OFF_P + HEADS * 64 * PROW)        // 2401
#define OFF_BIAS (OFF_MASK + NTOK * NTOK)           // 676
#define OFF_RIDX (OFF_BIAS + 169 * HEADS)           // 2401 ints
#define SMEM_FLOATS (OFF_RIDX + NTOK * NTOK)        // 54246 floats
#define SMEM_BYTES  (SMEM_FLOATS * 4)               // 216984 bytes

__device__ __forceinline__ float tf32r(float x) {
    uint32_t u;
    asm("cvt.rna.tf32.f32 %0, %1;" : "=r"(u) : "f"(x));
    return __uint_as_float(u);
}

__device__ __forceinline__ void mma8(float* d, const uint32_t* a, const uint32_t* b) {
    asm volatile(
        "mma.sync.aligned.m16n8k8.row.col.f32.tf32.tf32.f32 "
        "{%0,%1,%2,%3}, {%4,%5,%6,%7}, {%8,%9}, {%0,%1,%2,%3};\n"
        : "+f"(d[0]), "+f"(d[1]), "+f"(d[2]), "+f"(d[3])
        : "r"(a[0]), "r"(a[1]), "r"(a[2]), "r"(a[3]), "r"(b[0]), "r"(b[1]));
}

__global__ __launch_bounds__(NTHR, 1)
void lpwin_kernel(const float* __restrict__ x,
                  const float* __restrict__ mask,
                  const float* __restrict__ qkv_w,
                  const float* __restrict__ proj_w,
                  const float* __restrict__ proj_b,
                  const float* __restrict__ bias_table,
                  const float* __restrict__ alpha,
                  const int*   __restrict__ rel_idx,
                  float* __restrict__ out,
                  int nwin)
{
    extern __shared__ float sm[];
    const int b    = blockIdx.x;
    const int tid  = threadIdx.x;
    const int wid  = tid >> 5;    // 0..31
    const int lane = tid & 31;
    const int g    = lane >> 2;   // mma groupID
    const int t    = lane & 3;    // mma threadID-in-group

    float* xs = sm + OFF_XS;
    float* Qs = sm + OFF_Q;
    float* Ks = sm + OFF_K;
    float* Vs = sm + OFF_VT;
    float* Ps = sm + OFF_P;
    float* Ws = sm + OFF_P;       // weight staging aliases P (live ranges disjoint)
    float* Ms = sm + OFF_MASK;
    float* Bt = sm + OFF_BIAS;
    int*   Ri = (int*)(sm + OFF_RIDX);

    // ---------------- Phase 1: stage inputs ----------------
    const float* xb = x + (size_t)b * (NTOK * CDIM);
    for (int i = tid; i < NTOK * 32; i += NTHR) {
        int r = i >> 5, c4 = (i & 31) << 2;
        float4 v = *(const float4*)(xb + r * CDIM + c4);
        v.x = tf32r(v.x); v.y = tf32r(v.y); v.z = tf32r(v.z); v.w = tf32r(v.w);
        *(float4*)(xs + r * XROW + c4) = v;
    }
    for (int i = tid; i < HEADS * HD * VROW; i += NTHR) Vs[i] = 0.f;  // zero incl. k-pad cols
    {
        const int widx = b % nwin;
        const float* mb = mask + (size_t)widx * (NTOK * NTOK);
        for (int i = tid; i < NTOK * NTOK; i += NTHR) Ms[i] = mb[i];
    }
    for (int i = tid; i < NTOK * NTOK; i += NTHR) Ri[i] = rel_idx[i];
    for (int i = tid; i < 169 * HEADS; i += NTHR) Bt[i] = bias_table[i];
    __syncthreads();

    // ---------------- Phase 2: QKV GEMM (tf32 mma), W streamed via smem ----------------
    // 32 warps: warp = (mt = wid>>3) x (6 n-tiles at n0 = (wid&7)*48)
    {
        float acc[6][4];
        #pragma unroll
        for (int nt = 0; nt < 6; ++nt)
            #pragma unroll
            for (int e = 0; e < 4; ++e) acc[nt][e] = 0.f;

        const int mt = wid >> 3;
        const int n0 = (wid & 7) * 48;
        for (int kc = 0; kc < 4; ++kc) {          // k-chunks of 32
            for (int i = tid; i < 384 * 8; i += NTHR) {
                int n = i >> 3, q4 = (i & 7) << 2;
                float4 v = *(const float4*)(qkv_w + n * CDIM + kc * 32 + q4);
                v.x = tf32r(v.x); v.y = tf32r(v.y); v.z = tf32r(v.z); v.w = tf32r(v.w);
                *(float4*)(Ws + n * QROW + q4) = v;
            }
            __syncthreads();
            #pragma unroll
            for (int k8 = 0; k8 < 4; ++k8) {
                const int kk = k8 * 8;
                const float* ap = xs + (mt * 16 + g) * XROW + kc * 32 + kk + t;
                uint32_t af[4];
                af[0] = __float_as_uint(ap[0]);
                af[1] = __float_as_uint(ap[8 * XROW]);
                af[2] = __float_as_uint(ap[4]);
                af[3] = __float_as_uint(ap[8 * XROW + 4]);
                #pragma unroll
                for (int nt = 0; nt < 6; ++nt) {
                    const float* bp = Ws + (n0 + nt * 8 + g) * QROW + kk + t;
                    uint32_t bf[2];
                    bf[0] = __float_as_uint(bp[0]);
                    bf[1] = __float_as_uint(bp[4]);
                    mma8(acc[nt], af, bf);
                }
            }
            __syncthreads();
        }
        // scatter C fragments to Q / K / V^T
        #pragma unroll
        for (int nt = 0; nt < 6; ++nt)
            #pragma unroll
            for (int e = 0; e < 4; ++e) {
                int row = mt * 16 + g + (e >> 1) * 8;
                if (row >= NTOK) continue;
                int n = n0 + nt * 8 + 2 * t + (e & 1);
                float v = acc[nt][e];
                if (n < 128) {
                    Qs[(n >> 5) * 64 * QROW + row * QROW + (n & 31)] = v;
                } else if (n < 256) {
                    int m = n - 128;
                    Ks[(m >> 5) * 56 * QROW + row * QROW + (m & 31)] = v;
                } else {
                    int m = n - 256;
                    Vs[(m >> 5) * HD * VROW + (m & 31) * VROW + row] = tf32r(v);
                }
            }
    }
    __syncthreads();

    // ---------------- Phase 3: per-head attention (8 warps / head) ----------------
    const int h   = wid >> 3;
    const int sub = wid & 7;
    float* Qh = Qs + h * 64 * QROW;
    float* Kh = Ks + h * 56 * QROW;
    float* Vh = Vs + h * HD * VROW;
    float* Ph = Ps + h * 64 * PROW;

    // 3a: L2 normalize (p=2); alpha folded into q_hat. 4-row ILP to hide SHFL latency.
    {
        const bool isQ = (sub < 4);
        const int  part = isQ ? sub : (sub - 4);
        const float sc = isQ ? alpha[h] : 1.f;
        float* T = isQ ? Qh : Kh;
        const int rs = part * 13;
        const int re = min(rs + 13, NTOK);
        for (int r = rs; r < re; r += 4) {
            float v[4], ss[4]; int rr[4];
            #pragma unroll
            for (int j = 0; j < 4; ++j) {
                rr[j] = min(r + j, re - 1);
                v[j]  = T[rr[j] * QROW + lane];
                ss[j] = v[j] * v[j];
            }
            #pragma unroll
            for (int o = 16; o > 0; o >>= 1) {
                #pragma unroll
                for (int j = 0; j < 4; ++j) ss[j] += __shfl_xor_sync(0xffffffffu, ss[j], o);
            }
            #pragma unroll
            for (int j = 0; j < 4; ++j) {
                if (r + j < re) {
                    float inv = sc / (sqrtf(ss[j]) + 1e-6f);
                    T[rr[j] * QROW + lane] = tf32r(v[j] * inv);
                }
            }
        }
    }
    __syncthreads();

    // 3b: S = alpha * q_hat k_hat^T + rpb + mask  (one n-tile per warp; warp 7 of each head idle)
    if (sub < 7) {
        const int nt = sub;
        uint32_t bfv[4][2];
        #pragma unroll
        for (int k8 = 0; k8 < 4; ++k8) {
            const float* bp = Kh + (nt * 8 + g) * QROW + k8 * 8 + t;
            bfv[k8][0] = __float_as_uint(bp[0]);
            bfv[k8][1] = __float_as_uint(bp[4]);
        }
        #pragma unroll
        for (int mt = 0; mt < 4; ++mt) {
            float c[4] = {0.f, 0.f, 0.f, 0.f};
            #pragma unroll
            for (int k8 = 0; k8 < 4; ++k8) {
                const float* ap = Qh + (mt * 16 + g) * QROW + k8 * 8 + t;
                uint32_t af[4];
                af[0] = __float_as_uint(ap[0]);
                af[1] = __float_as_uint(ap[8 * QROW]);
                af[2] = __float_as_uint(ap[4]);
                af[3] = __float_as_uint(ap[8 * QROW + 4]);
                mma8(c, af, bfv[k8]);
            }
            #pragma unroll
            for (int e = 0; e < 4; ++e) {
                int i = mt * 16 + g + (e >> 1) * 8;
                int j = nt * 8 + 2 * t + (e & 1);
                float v = c[e];
                if (i < NTOK && j < NTOK)
                    v += Bt[Ri[i * NTOK + j] * HEADS + h] + Ms[i * NTOK + j];
                Ph[i * PROW + j] = v;
            }
        }
    }
    __syncthreads();

    // 3c: row softmax (no max-subtract: logits bounded), strided rows, 2-row ILP;
    //     zero pad cols 49..55 (k-pad for PV mma)
    {
        for (int i0 = sub; i0 < NTOK; i0 += 16) {
            const int ia = i0;
            const int ib = i0 + 8;
            const bool hasb = (ib < NTOK);
            const int ibc = hasb ? ib : ia;
            float e1a = __expf(Ph[ia * PROW + lane]);
            float e2a = (lane < 17) ? __expf(Ph[ia * PROW + 32 + lane]) : 0.f;
            float e1b = __expf(Ph[ibc * PROW + lane]);
            float e2b = (lane < 17) ? __expf(Ph[ibc * PROW + 32 + lane]) : 0.f;
            float sa = e1a + e2a;
            float sb = e1b + e2b;
            #pragma unroll
            for (int o = 16; o > 0; o >>= 1) {
                sa += __shfl_xor_sync(0xffffffffu, sa, o);
                sb += __shfl_xor_sync(0xffffffffu, sb, o);
            }
            float inva = 1.f / sa;
            Ph[ia * PROW + lane] = tf32r(e1a * inva);
            if (lane < 24) Ph[ia * PROW + 32 + lane] = (lane < 17) ? tf32r(e2a * inva) : 0.f;
            if (hasb) {
                float invb = 1.f / sb;
                Ph[ib * PROW + lane] = tf32r(e1b * invb);
                if (lane < 24) Ph[ib * PROW + 32 + lane] = (lane < 17) ? tf32r(e2b * invb) : 0.f;
            }
        }
    }
    __syncthreads();

    // 3d: O = P V  (V^T layout): 16 tiles per head over 8 warps -> 1 n-tile, 2 m-tiles each
    {
        const int nt  = sub >> 1;
        const int mt0 = (sub & 1) * 2;
        uint32_t bfv[7][2];
        #pragma unroll
        for (int k8 = 0; k8 < 7; ++k8) {
            const float* bp = Vh + (nt * 8 + g) * VROW + k8 * 8 + t;
            bfv[k8][0] = __float_as_uint(bp[0]);
            bfv[k8][1] = __float_as_uint(bp[4]);
        }
        #pragma unroll
        for (int mi = 0; mi < 2; ++mi) {
            const int mt = mt0 + mi;
            float c[4] = {0.f, 0.f, 0.f, 0.f};
            #pragma unroll
            for (int k8 = 0; k8 < 7; ++k8) {
                const float* ap = Ph + (mt * 16 + g) * PROW + k8 * 8 + t;
                uint32_t af[4];
                af[0] = __float_as_uint(ap[0]);
                af[1] = __float_as_uint(ap[8 * PROW]);
                af[2] = __float_as_uint(ap[4]);
                af[3] = __float_as_uint(ap[8 * PROW + 4]);
                mma8(c, af, bfv[k8]);
            }
            #pragma unroll
            for (int e = 0; e < 4; ++e) {
                int i = mt * 16 + g + (e >> 1) * 8;
                if (i >= NTOK) continue;
                int d = nt * 8 + 2 * t + (e & 1);
                xs[i * XROW + h * HD + d] = tf32r(c[e]);
            }
        }
    }
    __syncthreads();

    // ---------------- Phase 4: output projection + bias ----------------
    // 64 tiles (4 mt x 16 nt) over 32 warps: warp = (nt = wid&15) x (2 m-tiles)
    {
        float acc[2][4];
        #pragma unroll
        for (int mi = 0; mi < 2; ++mi)
            #pragma unroll
            for (int e = 0; e < 4; ++e) acc[mi][e] = 0.f;

        const int n0  = (wid & 15) * 8;
        const int mt0 = (wid >> 4) * 2;
        for (int kc = 0; kc < 2; ++kc) {          // k-chunks of 64
            for (int i = tid; i < 128 * 16; i += NTHR) {
                int n = i >> 4, q4 = (i & 15) << 2;
                float4 v = *(const float4*)(proj_w + n * CDIM + kc * 64 + q4);
                v.x = tf32r(v.x); v.y = tf32r(v.y); v.z = tf32r(v.z); v.w = tf32r(v.w);
                *(float4*)(Ws + n * 68 + q4) = v;
            }
            __syncthreads();
            #pragma unroll
            for (int k8 = 0; k8 < 8; ++k8) {
                uint32_t bfv[2];
                const float* bp = Ws + (n0 + g) * 68 + k8 * 8 + t;
                bfv[0] = __float_as_uint(bp[0]);
                bfv[1] = __float_as_uint(bp[4]);
                #pragma unroll
                for (int mi = 0; mi < 2; ++mi) {
                    const float* ap = xs + ((mt0 + mi) * 16 + g) * XROW + kc * 64 + k8 * 8 + t;
                    uint32_t af[4];
                    af[0] = __float_as_uint(ap[0]);
                    af[1] = __float_as_uint(ap[8 * XROW]);
                    af[2] = __float_as_uint(ap[4]);
                    af[3] = __float_as_uint(ap[8 * XROW + 4]);
                    mma8(acc[mi], af, bfv);
                }
            }
            __syncthreads();
        }
        // stash into xs, then coalesced float4 store with bias
        #pragma unroll
        for (int mi = 0; mi < 2; ++mi)
            #pragma unroll
            for (int e = 0; e < 4; ++e) {
                int row = (mt0 + mi) * 16 + g + (e >> 1) * 8;
                if (row >= NTOK) continue;
                int col = n0 + 2 * t + (e & 1);
                xs[row * XROW + col] = acc[mi][e];
            }
        __syncthreads();
        float* ob = out + (size_t)b * (NTOK * CDIM);
        for (int i = tid; i < NTOK * 32; i += NTHR) {
            int r = i >> 5, c4 = (i & 31) << 2;
            float4 v  = *(const float4*)(xs + r * XROW + c4);
            float4 pb = *(const float4*)(proj_b + c4);
            v.x += pb.x; v.y += pb.y; v.z += pb.z; v.w += pb.w;
            *(float4*)(ob + r * CDIM + c4) = v;
        }
    }
}

extern "C" void kernel_launch(void* const* d_in, const int* in_sizes, int n_in,
                              void* d_out, int out_size) {
    const float* x    = (const float*)d_in[0];
    const float* mask = (const float*)d_in[1];
    const float* qkvw = (const float*)d_in[2];
    const float* pw   = (const float*)d_in[3];
    const float* pb   = (const float*)d_in[4];
    const float* bt   = (const float*)d_in[5];
    const float* al   = (const float*)d_in[6];
    const int*   ri   = (const int*)d_in[7];
    float* out = (float*)d_out;

    int B  = in_sizes[0] / (NTOK * CDIM);
    int NW = in_sizes[1] / (NTOK * NTOK);

    cudaFuncSetAttribute(lpwin_kernel, cudaFuncAttributeMaxDynamicSharedMemorySize, SMEM_BYTES);
    lpwin_kernel<<<B, NTHR, SMEM_BYTES>>>(x, mask, qkvw, pw, pb, bt, al, ri, out, NW);
}